// round 5
// baseline (speedup 1.0000x reference)
#include <cuda_runtime.h>
#include <cuda_bf16.h>
#include <cstdint>

#define DIN  256
#define DOUT 64
#define NMAX 200000

// ---------------- device scratch (no allocations allowed) ----------------------
__device__ float g_eprime[(size_t)NMAX * DOUT];
__device__ float g_ssrc[NMAX];
__device__ __nv_bfloat16 g_Whi[DOUT * DIN];
__device__ __nv_bfloat16 g_Wlo[DOUT * DIN];
__device__ int g_mask_is_byte;

// ---------------- helpers -------------------------------------------------------
__device__ __forceinline__ uint32_t smem_u32(const void* p) {
    uint32_t a;
    asm("{ .reg .u64 t; cvta.to.shared.u64 t, %1; cvt.u32.u64 %0, t; }" : "=r"(a) : "l"(p));
    return a;
}
#define SWZ128(bo) ((bo) ^ (((bo) >> 3) & 0x70))

__device__ __forceinline__ void ldsm_x4(uint32_t* r, uint32_t addr) {
    asm volatile("ldmatrix.sync.aligned.m8n8.x4.shared.b16 {%0,%1,%2,%3}, [%4];"
                 : "=r"(r[0]), "=r"(r[1]), "=r"(r[2]), "=r"(r[3]) : "r"(addr));
}
__device__ __forceinline__ void mma_bf16(float* c, const uint32_t* a,
                                         uint32_t b0, uint32_t b1) {
    asm volatile("mma.sync.aligned.m16n8k16.row.col.f32.bf16.bf16.f32 "
                 "{%0,%1,%2,%3}, {%4,%5,%6,%7}, {%8,%9}, {%0,%1,%2,%3};"
                 : "+f"(c[0]), "+f"(c[1]), "+f"(c[2]), "+f"(c[3])
                 : "r"(a[0]), "r"(a[1]), "r"(a[2]), "r"(a[3]), "r"(b0), "r"(b1));
}
// split a float into bf16 hi (round-half-up, 2 int ops) + fp32 residual
__device__ __forceinline__ uint32_t hi_bits(float x) {
    return (__float_as_uint(x) + 0x8000u) & 0xFFFF0000u;
}

// ---------------- smem layout (dynamic, 64 KB) ------------------------------------
// [0,32K): W hi  [32K,64K): W lo   (layout: [chunk c][64 n][128B k], SW128/blk)
#define OFF_WHI 0
#define OFF_WLO 32768
#define SMEM_TOTAL 65536

// ---------------- W split (once per launch) --------------------------------------
__global__ void wsplit_kernel(const float* __restrict__ W) {
    int i = blockIdx.x * 256 + threadIdx.x;
    if (i < DOUT * DIN) {
        float x  = W[i];
        float hf = __uint_as_float(hi_bits(x));
        g_Whi[i] = __float2bfloat16_rn(hf);
        g_Wlo[i] = __float2bfloat16_rn(x - hf);
    }
}

// ---------------- Phase 1: mma.sync bf16 3-pass GEMM, A streamed from gmem --------
__global__ __launch_bounds__(256, 2) void gemm_mma_kernel(const float* __restrict__ X,
                                                          const float* __restrict__ a_src,
                                                          int Ntot) {
    extern __shared__ char smem[];
    const uint32_t sb = smem_u32(smem);

    const int t    = threadIdx.x;
    const int lane = t & 31;
    const int wid  = t >> 5;
    const int row0 = blockIdx.x * 128;

    const int m0 = (wid & 3) * 32;   // warp m-offset
    const int n0 = (wid >> 2) * 32;  // warp n-offset

    // B ldmatrix lane geometry (non-trans on [n][k] rows)
    const int bn_lm = (lane & 7) + (((lane >> 4) & 1) << 3);
    const int bk_lm = ((lane >> 3) & 1) * 16;

    // a_src values for this lane's output columns
    float sa8[8];
#pragma unroll
    for (int nt = 0; nt < 4; nt++) {
        int col = n0 + nt * 8 + ((lane & 3) << 1);
        sa8[2 * nt]     = __ldg(&a_src[col]);
        sa8[2 * nt + 1] = __ldg(&a_src[col + 1]);
    }

    // ---- stage W (hi+lo, 64KB) into smem, swizzled per 128B row -------------------
#pragma unroll
    for (int i = 0; i < 8; i++) {
        int gidx = t + i * 256;                 // uint4 index into 32KB
        int n    = gidx >> 5;
        int rem  = (gidx & 31) * 16;            // byte offset in 512B global row
        int c    = rem >> 7;
        int kb   = rem & 127;
        uint32_t so = (uint32_t)c * 8192 + SWZ128((uint32_t)n * 128 + kb);
        *(uint4*)(smem + OFF_WHI + so) = *(const uint4*)((const char*)g_Whi + (size_t)gidx * 16);
        *(uint4*)(smem + OFF_WLO + so) = *(const uint4*)((const char*)g_Wlo + (size_t)gidx * 16);
    }

    // ---- A fragment gmem pointers: lane holds (r, r+8) x (k, k+8) float2 ----------
    const int r_in = lane >> 2, kq = (lane & 3) * 2;
    const float* pA[2][2];   // [mt][0: row r, 1: row r+8]
#pragma unroll
    for (int mt = 0; mt < 2; mt++) {
        int r  = row0 + m0 + mt * 16 + r_in;
        int r8 = r + 8;
        if (r  >= Ntot) r  = Ntot - 1;
        if (r8 >= Ntot) r8 = Ntot - 1;
        pA[mt][0] = X + (size_t)r  * DIN + kq;
        pA[mt][1] = X + (size_t)r8 * DIN + kq;
    }

    float acc[2][4][4];
#pragma unroll
    for (int i = 0; i < 2; i++)
#pragma unroll
        for (int j = 0; j < 4; j++)
#pragma unroll
            for (int q = 0; q < 4; q++) acc[i][j][q] = 0.f;

    // prologue: load k-step 0 fragments
    float2 cur[2][4], nxt[2][4];
#pragma unroll
    for (int mt = 0; mt < 2; mt++) {
        cur[mt][0] = *(const float2*)(pA[mt][0]);
        cur[mt][1] = *(const float2*)(pA[mt][1]);
        cur[mt][2] = *(const float2*)(pA[mt][0] + 8);
        cur[mt][3] = *(const float2*)(pA[mt][1] + 8);
    }
    __syncthreads();   // W staged

#pragma unroll 4
    for (int s = 0; s < 16; s++) {
        // prefetch next k-step
        if (s < 15) {
            const int kn = (s + 1) * 16;
#pragma unroll
            for (int mt = 0; mt < 2; mt++) {
                nxt[mt][0] = *(const float2*)(pA[mt][0] + kn);
                nxt[mt][1] = *(const float2*)(pA[mt][1] + kn);
                nxt[mt][2] = *(const float2*)(pA[mt][0] + kn + 8);
                nxt[mt][3] = *(const float2*)(pA[mt][1] + kn + 8);
            }
        }
        // convert current fragments to bf16 hi/lo
        uint32_t ah[2][4], al[2][4];
#pragma unroll
        for (int mt = 0; mt < 2; mt++)
#pragma unroll
            for (int q = 0; q < 4; q++) {
                float fx = cur[mt][q].x, fy = cur[mt][q].y;
                uint32_t ha = hi_bits(fx), hb = hi_bits(fy);
                ah[mt][q] = __byte_perm(ha, hb, 0x7632);
                __nv_bfloat162 lo2 = __floats2bfloat162_rn(
                    fx - __uint_as_float(ha), fy - __uint_as_float(hb));
                al[mt][q] = *(uint32_t*)&lo2;
            }
        // B fragments from smem
        uint32_t bh[8], bl[8];
        const uint32_t wh_base = sb + OFF_WHI + (s >> 2) * 8192;
        const uint32_t wl_base = sb + OFF_WLO + (s >> 2) * 8192;
#pragma unroll
        for (int half = 0; half < 2; half++) {
            uint32_t bo = SWZ128((uint32_t)(n0 + half * 16 + bn_lm) * 128 +
                                 (s & 3) * 32 + bk_lm);
            ldsm_x4(bh + half * 4, wh_base + bo);
            ldsm_x4(bl + half * 4, wl_base + bo);
        }
        // 24 MMAs
#pragma unroll
        for (int nt = 0; nt < 4; nt++) {
            uint32_t bh0 = bh[2 * nt], bh1 = bh[2 * nt + 1];
            uint32_t bl0 = bl[2 * nt], bl1 = bl[2 * nt + 1];
#pragma unroll
            for (int mt = 0; mt < 2; mt++) {
                mma_bf16(acc[mt][nt], ah[mt], bh0, bh1);
                mma_bf16(acc[mt][nt], ah[mt], bl0, bl1);
                mma_bf16(acc[mt][nt], al[mt], bh0, bh1);
            }
        }
#pragma unroll
        for (int mt = 0; mt < 2; mt++)
#pragma unroll
            for (int q = 0; q < 4; q++) cur[mt][q] = nxt[mt][q];
    }

    // ---- epilogue: stores + fused ssrc ------------------------------------------
#pragma unroll
    for (int mt = 0; mt < 2; mt++) {
        int r = row0 + m0 + mt * 16 + (lane >> 2);
#pragma unroll
        for (int nt = 0; nt < 4; nt++) {
            int col = n0 + nt * 8 + ((lane & 3) << 1);
            if (r < Ntot)
                *(float2*)(g_eprime + (size_t)r * DOUT + col) =
                    make_float2(acc[mt][nt][0], acc[mt][nt][1]);
            if (r + 8 < Ntot)
                *(float2*)(g_eprime + (size_t)(r + 8) * DOUT + col) =
                    make_float2(acc[mt][nt][2], acc[mt][nt][3]);
        }
    }
    // partial dot with a_src per row (32 cols per warp), quad-reduced
    __syncthreads();                 // W reads done -> reuse smem for partials
    float* part = (float*)smem;      // [128][2]
#pragma unroll
    for (int mt = 0; mt < 2; mt++) {
        float p0 = 0.f, p1 = 0.f;
#pragma unroll
        for (int nt = 0; nt < 4; nt++) {
            p0 = fmaf(acc[mt][nt][0], sa8[2 * nt], p0);
            p0 = fmaf(acc[mt][nt][1], sa8[2 * nt + 1], p0);
            p1 = fmaf(acc[mt][nt][2], sa8[2 * nt], p1);
            p1 = fmaf(acc[mt][nt][3], sa8[2 * nt + 1], p1);
        }
        p0 += __shfl_xor_sync(0xffffffffu, p0, 1);
        p0 += __shfl_xor_sync(0xffffffffu, p0, 2);
        p1 += __shfl_xor_sync(0xffffffffu, p1, 1);
        p1 += __shfl_xor_sync(0xffffffffu, p1, 2);
        if ((lane & 3) == 0) {
            int rl0 = m0 + mt * 16 + (lane >> 2);
            part[rl0 * 2 + (n0 >> 5)]       = p0;
            part[(rl0 + 8) * 2 + (n0 >> 5)] = p1;
        }
    }
    __syncthreads();
    if (t < 128) {
        int gr = row0 + t;
        if (gr < Ntot) {
            float s = part[t * 2] + part[t * 2 + 1];
            g_ssrc[gr] = (s >= 0.f) ? s : 0.2f * s;
        }
    }
}

// ---------------- mask dtype probe: bool(1B) vs int32 ----------------------------
__global__ void detect_kernel(const unsigned char* __restrict__ m) {
    int t = threadIdx.x;
    int f = 0;
    for (int i = t; i < 256; i += 32)
        if ((i & 3) && m[i]) f = 1;
    unsigned b = __ballot_sync(0xffffffffu, f);
    if (t == 0) g_mask_is_byte = (b != 0);
}

// ---------------- Phase 2: masked softmax + weighted gather-sum ------------------
__global__ __launch_bounds__(256) void agg_kernel(const int* __restrict__ neighs,
                                                  const void* __restrict__ mask_raw,
                                                  float* __restrict__ out,
                                                  int B, int L) {
    __shared__ float sw[8][64];
    __shared__ int   sidx[8][64];

    const int w    = threadIdx.x >> 5;
    const int lane = threadIdx.x & 31;
    const int row  = blockIdx.x * 8 + w;
    if (row >= B) return;

    const bool maskb = (g_mask_is_byte != 0);
    const unsigned char* mk8  = (const unsigned char*)mask_raw + (size_t)row * L;
    const int*           mk32 = (const int*)mask_raw + (size_t)row * L;
    const int* nb = neighs + (size_t)row * L;

    int   i0 = 0, i1 = 0;
    float s0 = -3e38f, s1 = -3e38f;
    bool  v0 = false, v1 = false;
    if (lane < L) {
        v0 = maskb ? (mk8[lane] != 0) : (mk32[lane] != 0);
        if (v0) { i0 = nb[lane]; s0 = g_ssrc[i0]; }
    }
    int l1 = lane + 32;
    if (l1 < L) {
        v1 = maskb ? (mk8[l1] != 0) : (mk32[l1] != 0);
        if (v1) { i1 = nb[l1]; s1 = g_ssrc[i1]; }
    }

    float m = fmaxf(s0, s1);
#pragma unroll
    for (int o = 16; o; o >>= 1) m = fmaxf(m, __shfl_xor_sync(0xffffffffu, m, o));
    float e0 = v0 ? __expf(s0 - m) : 0.f;
    float e1 = v1 ? __expf(s1 - m) : 0.f;
    float ssum = e0 + e1;
#pragma unroll
    for (int o = 16; o; o >>= 1) ssum += __shfl_xor_sync(0xffffffffu, ssum, o);
    float inv = 1.0f / ssum;

    unsigned bal0 = __ballot_sync(0xffffffffu, v0);
    unsigned bal1 = __ballot_sync(0xffffffffu, v1);
    int c0  = __popc(bal0);
    int cnt = c0 + __popc(bal1);
    unsigned lt = (1u << lane) - 1u;
    if (v0) { int p = __popc(bal0 & lt);       sw[w][p] = e0 * inv; sidx[w][p] = i0; }
    if (v1) { int p = c0 + __popc(bal1 & lt);  sw[w][p] = e1 * inv; sidx[w][p] = i1; }
    __syncwarp();

    // unrolled x4 gather: 4 independent load streams, 2 accumulator pairs
    float a0 = 0.f, a1 = 0.f, b0 = 0.f, b1 = 0.f;
    const float* ep = g_eprime + 2 * lane;
    int l = 0;
    for (; l + 4 <= cnt; l += 4) {
        float w0 = sw[w][l],     w1 = sw[w][l + 1];
        float w2 = sw[w][l + 2], w3 = sw[w][l + 3];
        size_t j0 = (size_t)sidx[w][l] * DOUT,     j1 = (size_t)sidx[w][l + 1] * DOUT;
        size_t j2 = (size_t)sidx[w][l + 2] * DOUT, j3 = (size_t)sidx[w][l + 3] * DOUT;
        float2 q0 = *(const float2*)(ep + j0);
        float2 q1 = *(const float2*)(ep + j1);
        float2 q2 = *(const float2*)(ep + j2);
        float2 q3 = *(const float2*)(ep + j3);
        a0 = fmaf(w0, q0.x, a0); a1 = fmaf(w0, q0.y, a1);
        b0 = fmaf(w1, q1.x, b0); b1 = fmaf(w1, q1.y, b1);
        a0 = fmaf(w2, q2.x, a0); a1 = fmaf(w2, q2.y, a1);
        b0 = fmaf(w3, q3.x, b0); b1 = fmaf(w3, q3.y, b1);
    }
    for (; l < cnt; l++) {
        float wgt = sw[w][l];
        float2 q = *(const float2*)(ep + (size_t)sidx[w][l] * DOUT);
        a0 = fmaf(wgt, q.x, a0); a1 = fmaf(wgt, q.y, a1);
    }
    *(float2*)(&out[(size_t)row * DOUT + 2 * lane]) = make_float2(a0 + b0, a1 + b1);
}

// -----------------------------------------------------------------------------------
extern "C" void kernel_launch(void* const* d_in, const int* in_sizes, int n_in,
                              void* d_out, int out_size) {
    const int*   neighs = (const int*)d_in[0];
    const void*  mask   = d_in[1];
    const float* embed  = (const float*)d_in[3];
    const float* W      = (const float*)d_in[4];
    const float* a_src  = (const float*)d_in[5];

    const int B = in_sizes[2];
    const int L = in_sizes[0] / B;
    const int N = in_sizes[3] / DIN;

    cudaFuncSetAttribute(gemm_mma_kernel,
                         cudaFuncAttributeMaxDynamicSharedMemorySize, SMEM_TOTAL);

    wsplit_kernel<<<(DOUT * DIN + 255) / 256, 256>>>(W);
    gemm_mma_kernel<<<(N + 127) / 128, 256, SMEM_TOTAL>>>(embed, a_src, N);
    detect_kernel<<<1, 32>>>((const unsigned char*)mask);
    agg_kernel<<<(B + 7) / 8, 256>>>(neighs, mask, (float*)d_out, B, L);
}

// round 7
// speedup vs baseline: 1.1656x; 1.1656x over previous
#include <cuda_runtime.h>
#include <cuda_bf16.h>
#include <cstdint>

#define DIN  256
#define DOUT 64
#define NMAX 200000

// ---------------- device scratch (no allocations allowed) ----------------------
__device__ float g_eprime[(size_t)NMAX * DOUT];
__device__ float g_ssrc[NMAX];
__device__ __nv_bfloat16 g_Whi[DOUT * DIN];
__device__ __nv_bfloat16 g_Wlo[DOUT * DIN];
__device__ int g_mask_is_byte;

// ---------------- helpers -------------------------------------------------------
__device__ __forceinline__ uint32_t smem_u32(const void* p) {
    uint32_t a;
    asm("{ .reg .u64 t; cvta.to.shared.u64 t, %1; cvt.u32.u64 %0, t; }" : "=r"(a) : "l"(p));
    return a;
}
#define SWZ128(bo) ((bo) ^ (((bo) >> 3) & 0x70))

__device__ __forceinline__ void ldsm_x4(uint32_t* r, uint32_t addr) {
    asm volatile("ldmatrix.sync.aligned.m8n8.x4.shared.b16 {%0,%1,%2,%3}, [%4];"
                 : "=r"(r[0]), "=r"(r[1]), "=r"(r[2]), "=r"(r[3]) : "r"(addr));
}
__device__ __forceinline__ void mma_bf16(float* c, const uint32_t* a,
                                         uint32_t b0, uint32_t b1) {
    asm volatile("mma.sync.aligned.m16n8k16.row.col.f32.bf16.bf16.f32 "
                 "{%0,%1,%2,%3}, {%4,%5,%6,%7}, {%8,%9}, {%0,%1,%2,%3};"
                 : "+f"(c[0]), "+f"(c[1]), "+f"(c[2]), "+f"(c[3])
                 : "r"(a[0]), "r"(a[1]), "r"(a[2]), "r"(a[3]), "r"(b0), "r"(b1));
}
// split a float into bf16 hi (round-half-up, 2 int ops) + fp32 residual
__device__ __forceinline__ uint32_t hi_bits(float x) {
    return (__float_as_uint(x) + 0x8000u) & 0xFFFF0000u;
}

// ---------------- smem layout (dynamic, 96 KB) ------------------------------------
#define OFF_WHI 0
#define OFF_WLO 32768
#define OFF_AHI 65536
#define OFF_ALO 81920
#define SMEM_TOTAL 98304

// ---------------- W split (once per launch) --------------------------------------
__global__ void wsplit_kernel(const float* __restrict__ W) {
    int i = blockIdx.x * 256 + threadIdx.x;
    if (i < DOUT * DIN) {
        float x  = W[i];
        float hf = __uint_as_float(hi_bits(x));
        g_Whi[i] = __float2bfloat16_rn(hf);
        g_Wlo[i] = __float2bfloat16_rn(x - hf);
    }
}

// ---------------- Phase 1: mma.sync bf16 3-pass GEMM + fused ssrc (R4 layout) ------
__global__ __launch_bounds__(256, 2) void gemm_mma_kernel(const float* __restrict__ X,
                                                          const float* __restrict__ a_src,
                                                          int Ntot) {
    extern __shared__ char smem[];
    const uint32_t sb = smem_u32(smem);

    const int t    = threadIdx.x;
    const int lane = t & 31;
    const int wid  = t >> 5;
    const int row0 = blockIdx.x * 128;

    const int m0 = (wid & 3) * 32;
    const int n0 = (wid >> 2) * 32;

    const int srow = t >> 3, g = t & 7;
    const int r_lm  = (lane & 7) | (((lane >> 3) & 1) << 3);
    const int klane = ((lane >> 4) & 1) * 16;
    const int bn_lm = (lane & 7) + (((lane >> 4) & 1) << 3);
    const int bk_lm = ((lane >> 3) & 1) * 16;

    float sa8[8];
#pragma unroll
    for (int nt = 0; nt < 4; nt++) {
        int col = n0 + nt * 8 + ((lane & 3) << 1);
        sa8[2 * nt]     = __ldg(&a_src[col]);
        sa8[2 * nt + 1] = __ldg(&a_src[col + 1]);
    }

    // stage W (hi+lo, 64KB) into smem, swizzled per 128B row
#pragma unroll
    for (int i = 0; i < 8; i++) {
        int gidx = t + i * 256;
        int n    = gidx >> 5;
        int rem  = (gidx & 31) * 16;
        int c    = rem >> 7;
        int kb   = rem & 127;
        uint32_t so = (uint32_t)c * 8192 + SWZ128((uint32_t)n * 128 + kb);
        *(uint4*)(smem + OFF_WHI + so) = *(const uint4*)((const char*)g_Whi + (size_t)gidx * 16);
        *(uint4*)(smem + OFF_WLO + so) = *(const uint4*)((const char*)g_Wlo + (size_t)gidx * 16);
    }

    float acc[2][4][4];
#pragma unroll
    for (int i = 0; i < 2; i++)
#pragma unroll
        for (int j = 0; j < 4; j++)
#pragma unroll
            for (int q = 0; q < 4; q++) acc[i][j][q] = 0.f;

    size_t grow[4];
#pragma unroll
    for (int p = 0; p < 4; p++) {
        int r = row0 + srow + 32 * p;
        grow[p] = (size_t)((r < Ntot) ? r : (Ntot - 1));
    }

    float4 va[4][2];
#pragma unroll
    for (int p = 0; p < 4; p++) {
        const float* src = X + grow[p] * DIN + g * 8;
        va[p][0] = *(const float4*)(src);
        va[p][1] = *(const float4*)(src + 4);
    }
#pragma unroll
    for (int p = 0; p < 4; p++) {
        uint32_t rh[4], rl[4];
        float f[8] = {va[p][0].x, va[p][0].y, va[p][0].z, va[p][0].w,
                      va[p][1].x, va[p][1].y, va[p][1].z, va[p][1].w};
#pragma unroll
        for (int q = 0; q < 4; q++) {
            uint32_t ha = hi_bits(f[2 * q]), hb = hi_bits(f[2 * q + 1]);
            rh[q] = __byte_perm(ha, hb, 0x7632);
            __nv_bfloat162 lo2 = __floats2bfloat162_rn(
                f[2 * q] - __uint_as_float(ha), f[2 * q + 1] - __uint_as_float(hb));
            rl[q] = *(uint32_t*)&lo2;
        }
        uint32_t bo = SWZ128((uint32_t)(srow + 32 * p) * 128 + g * 16);
        *(uint4*)(smem + OFF_AHI + bo) = make_uint4(rh[0], rh[1], rh[2], rh[3]);
        *(uint4*)(smem + OFF_ALO + bo) = make_uint4(rl[0], rl[1], rl[2], rl[3]);
    }
    __syncthreads();

    for (int c = 0; c < 4; c++) {
        if (c < 3) {
            const int kc = (c + 1) * 64;
#pragma unroll
            for (int p = 0; p < 4; p++) {
                const float* src = X + grow[p] * DIN + kc + g * 8;
                va[p][0] = *(const float4*)(src);
                va[p][1] = *(const float4*)(src + 4);
            }
        }
        const uint32_t ah_base = sb + OFF_AHI;
        const uint32_t al_base = sb + OFF_ALO;
        const uint32_t wh_base = sb + OFF_WHI + c * 8192;
        const uint32_t wl_base = sb + OFF_WLO + c * 8192;
#pragma unroll
        for (int ks = 0; ks < 4; ks++) {
            uint32_t ah[2][4], al[2][4], bh[8], bl[8];
#pragma unroll
            for (int mt = 0; mt < 2; mt++) {
                uint32_t bo = SWZ128((uint32_t)(m0 + mt * 16 + r_lm) * 128 +
                                     ks * 32 + klane);
                ldsm_x4(ah[mt], ah_base + bo);
                ldsm_x4(al[mt], al_base + bo);
            }
#pragma unroll
            for (int half = 0; half < 2; half++) {
                uint32_t bo = SWZ128((uint32_t)(n0 + half * 16 + bn_lm) * 128 +
                                     ks * 32 + bk_lm);
                ldsm_x4(bh + half * 4, wh_base + bo);
                ldsm_x4(bl + half * 4, wl_base + bo);
            }
#pragma unroll
            for (int nt = 0; nt < 4; nt++) {
                uint32_t bh0 = bh[2 * nt], bh1 = bh[2 * nt + 1];
                uint32_t bl0 = bl[2 * nt], bl1 = bl[2 * nt + 1];
#pragma unroll
                for (int mt = 0; mt < 2; mt++) {
                    mma_bf16(acc[mt][nt], ah[mt], bh0, bh1);
                    mma_bf16(acc[mt][nt], ah[mt], bl0, bl1);
                    mma_bf16(acc[mt][nt], al[mt], bh0, bh1);
                }
            }
        }
        if (c < 3) {
            __syncthreads();
#pragma unroll
            for (int p = 0; p < 4; p++) {
                uint32_t rh[4], rl[4];
                float f[8] = {va[p][0].x, va[p][0].y, va[p][0].z, va[p][0].w,
                              va[p][1].x, va[p][1].y, va[p][1].z, va[p][1].w};
#pragma unroll
                for (int q = 0; q < 4; q++) {
                    uint32_t ha = hi_bits(f[2 * q]), hb = hi_bits(f[2 * q + 1]);
                    rh[q] = __byte_perm(ha, hb, 0x7632);
                    __nv_bfloat162 lo2 = __floats2bfloat162_rn(
                        f[2 * q] - __uint_as_float(ha), f[2 * q + 1] - __uint_as_float(hb));
                    rl[q] = *(uint32_t*)&lo2;
                }
                uint32_t bo = SWZ128((uint32_t)(srow + 32 * p) * 128 + g * 16);
                *(uint4*)(smem + OFF_AHI + bo) = make_uint4(rh[0], rh[1], rh[2], rh[3]);
                *(uint4*)(smem + OFF_ALO + bo) = make_uint4(rl[0], rl[1], rl[2], rl[3]);
            }
            __syncthreads();
        }
    }

    // epilogue: stores + fused ssrc
#pragma unroll
    for (int mt = 0; mt < 2; mt++) {
        int r = row0 + m0 + mt * 16 + (lane >> 2);
#pragma unroll
        for (int nt = 0; nt < 4; nt++) {
            int col = n0 + nt * 8 + ((lane & 3) << 1);
            if (r < Ntot)
                *(float2*)(g_eprime + (size_t)r * DOUT + col) =
                    make_float2(acc[mt][nt][0], acc[mt][nt][1]);
            if (r + 8 < Ntot)
                *(float2*)(g_eprime + (size_t)(r + 8) * DOUT + col) =
                    make_float2(acc[mt][nt][2], acc[mt][nt][3]);
        }
    }
    __syncthreads();
    float* part = (float*)smem;
#pragma unroll
    for (int mt = 0; mt < 2; mt++) {
        float p0 = 0.f, p1 = 0.f;
#pragma unroll
        for (int nt = 0; nt < 4; nt++) {
            p0 = fmaf(acc[mt][nt][0], sa8[2 * nt], p0);
            p0 = fmaf(acc[mt][nt][1], sa8[2 * nt + 1], p0);
            p1 = fmaf(acc[mt][nt][2], sa8[2 * nt], p1);
            p1 = fmaf(acc[mt][nt][3], sa8[2 * nt + 1], p1);
        }
        p0 += __shfl_xor_sync(0xffffffffu, p0, 1);
        p0 += __shfl_xor_sync(0xffffffffu, p0, 2);
        p1 += __shfl_xor_sync(0xffffffffu, p1, 1);
        p1 += __shfl_xor_sync(0xffffffffu, p1, 2);
        if ((lane & 3) == 0) {
            int rl0 = m0 + mt * 16 + (lane >> 2);
            part[rl0 * 2 + (n0 >> 5)]       = p0;
            part[(rl0 + 8) * 2 + (n0 >> 5)] = p1;
        }
    }
    __syncthreads();
    if (t < 128) {
        int gr = row0 + t;
        if (gr < Ntot) {
            float s = part[t * 2] + part[t * 2 + 1];
            g_ssrc[gr] = (s >= 0.f) ? s : 0.2f * s;
        }
    }
}

// ---------------- mask dtype probe: bool(1B) vs int32 ----------------------------
__global__ void detect_kernel(const unsigned char* __restrict__ m) {
    int t = threadIdx.x;
    int f = 0;
    for (int i = t; i < 256; i += 32)
        if ((i & 3) && m[i]) f = 1;
    unsigned b = __ballot_sync(0xffffffffu, f);
    if (t == 0) g_mask_is_byte = (b != 0);
}

// ---------------- Phase 2: 2 rows/warp, 16 lanes/row, float4 gathers --------------
__global__ __launch_bounds__(256) void agg_kernel(const int* __restrict__ neighs,
                                                  const void* __restrict__ mask_raw,
                                                  float* __restrict__ out,
                                                  int B, int L) {
    __shared__ float sw[8][2][64];
    __shared__ int   sidx[8][2][64];

    const int w    = threadIdx.x >> 5;
    const int lane = threadIdx.x & 31;
    const int half = lane >> 4;          // which row of the pair
    const int hl   = lane & 15;          // lane within 16-group
    const int row  = (blockIdx.x * 8 + w) * 2 + half;
    const bool rv  = (row < B);
    const int rowc = rv ? row : 0;       // clamped for pointer math

    const bool maskb = (g_mask_is_byte != 0);
    const unsigned char* mk8  = (const unsigned char*)mask_raw + (size_t)rowc * L;
    const int*           mk32 = (const int*)mask_raw + (size_t)rowc * L;
    const int* nb = neighs + (size_t)rowc * L;

    // up to 4 slots per lane: l = hl + 16j
    int   ix[4];
    float s[4];
    bool  v[4];
#pragma unroll
    for (int j = 0; j < 4; j++) {
        int l = hl + 16 * j;
        v[j] = false; s[j] = -3e38f; ix[j] = 0;
        if (rv && l < L) {
            v[j] = maskb ? (mk8[l] != 0) : (mk32[l] != 0);
            if (v[j]) { ix[j] = nb[l]; s[j] = g_ssrc[ix[j]]; }
        }
    }

    // width-16 softmax reductions
    float m = fmaxf(fmaxf(s[0], s[1]), fmaxf(s[2], s[3]));
#pragma unroll
    for (int o = 8; o; o >>= 1) m = fmaxf(m, __shfl_xor_sync(0xffffffffu, m, o));
    float e[4], ssum = 0.f;
#pragma unroll
    for (int j = 0; j < 4; j++) {
        e[j] = v[j] ? __expf(s[j] - m) : 0.f;
        ssum += e[j];
    }
#pragma unroll
    for (int o = 8; o; o >>= 1) ssum += __shfl_xor_sync(0xffffffffu, ssum, o);
    float inv = (ssum > 0.f) ? 1.0f / ssum : 0.f;

    // ballot compaction within 16-lane group, j-major ordering
    unsigned bal[4];
#pragma unroll
    for (int j = 0; j < 4; j++) bal[j] = __ballot_sync(0xffffffffu, v[j]);
    const unsigned hmask = 0xFFFFu << (half * 16);
    const unsigned lt    = ((1u << lane) - 1u) & hmask;
    int cnt = 0;
#pragma unroll
    for (int j = 0; j < 4; j++) {
        if (v[j]) {
            int p = cnt + __popc(bal[j] & lt);
            sw[w][half][p]   = e[j] * inv;
            sidx[w][half][p] = ix[j];
        }
        cnt += __popc(bal[j] & hmask);
    }
    __syncwarp();

    // warp-max trip count (predicated slots: weight=0, index clamped to 0)
    int cmax = max(cnt, __shfl_xor_sync(0xffffffffu, cnt, 16));

    // gather: lane owns dims 4*hl..4*hl+3 of its row; LDG.128 per neighbor
    float a0 = 0.f, a1 = 0.f, a2 = 0.f, a3 = 0.f;
    float b0 = 0.f, b1 = 0.f, b2 = 0.f, b3 = 0.f;
    const float* ep = g_eprime + 4 * hl;
    const float* swr = sw[w][half];
    const int*   sir = sidx[w][half];
    int l = 0;
    for (; l + 2 <= cmax; l += 2) {
        bool ok0 = (l < cnt), ok1 = (l + 1 < cnt);
        float w0 = ok0 ? swr[l]     : 0.f;
        float w1 = ok1 ? swr[l + 1] : 0.f;
        size_t j0 = ok0 ? (size_t)sir[l] * DOUT     : 0;
        size_t j1 = ok1 ? (size_t)sir[l + 1] * DOUT : 0;
        float4 q0 = *(const float4*)(ep + j0);
        float4 q1 = *(const float4*)(ep + j1);
        a0 = fmaf(w0, q0.x, a0); a1 = fmaf(w0, q0.y, a1);
        a2 = fmaf(w0, q0.z, a2); a3 = fmaf(w0, q0.w, a3);
        b0 = fmaf(w1, q1.x, b0); b1 = fmaf(w1, q1.y, b1);
        b2 = fmaf(w1, q1.z, b2); b3 = fmaf(w1, q1.w, b3);
    }
    if (l < cmax) {
        bool ok0 = (l < cnt);
        float w0 = ok0 ? swr[l] : 0.f;
        size_t j0 = ok0 ? (size_t)sir[l] * DOUT : 0;
        float4 q0 = *(const float4*)(ep + j0);
        a0 = fmaf(w0, q0.x, a0); a1 = fmaf(w0, q0.y, a1);
        a2 = fmaf(w0, q0.z, a2); a3 = fmaf(w0, q0.w, a3);
    }
    if (rv)
        *(float4*)(&out[(size_t)row * DOUT + 4 * hl]) =
            make_float4(a0 + b0, a1 + b1, a2 + b2, a3 + b3);
}

// -----------------------------------------------------------------------------------
extern "C" void kernel_launch(void* const* d_in, const int* in_sizes, int n_in,
                              void* d_out, int out_size) {
    const int*   neighs = (const int*)d_in[0];
    const void*  mask   = d_in[1];
    const float* embed  = (const float*)d_in[3];
    const float* W      = (const float*)d_in[4];
    const float* a_src  = (const float*)d_in[5];

    const int B = in_sizes[2];
    const int L = in_sizes[0] / B;
    const int N = in_sizes[3] / DIN;

    cudaFuncSetAttribute(gemm_mma_kernel,
                         cudaFuncAttributeMaxDynamicSharedMemorySize, SMEM_TOTAL);

    wsplit_kernel<<<(DOUT * DIN + 255) / 256, 256>>>(W);
    gemm_mma_kernel<<<(N + 127) / 128, 256, SMEM_TOTAL>>>(embed, a_src, N);
    detect_kernel<<<1, 32>>>((const unsigned char*)mask);
    agg_kernel<<<(B + 15) / 16, 256>>>(neighs, mask, (float*)d_out, B, L);
}

// round 8
// speedup vs baseline: 1.2342x; 1.0589x over previous
#include <cuda_runtime.h>
#include <cuda_bf16.h>
#include <cuda_fp16.h>
#include <cstdint>

#define DIN  256
#define DOUT 64
#define NMAX 200000

// ---------------- device scratch (no allocations allowed) ----------------------
__device__ __half g_eph[(size_t)NMAX * DOUT];   // projected embeddings, fp16
__device__ float  g_ssrc[NMAX];
__device__ int    g_mask_is_byte;

// ---------------- helpers -------------------------------------------------------
__device__ __forceinline__ uint32_t smem_u32(const void* p) {
    uint32_t a;
    asm("{ .reg .u64 t; cvta.to.shared.u64 t, %1; cvt.u32.u64 %0, t; }" : "=r"(a) : "l"(p));
    return a;
}
#define SWZ128(bo) ((bo) ^ (((bo) >> 3) & 0x70))

__device__ __forceinline__ void ldsm_x4(uint32_t* r, uint32_t addr) {
    asm volatile("ldmatrix.sync.aligned.m8n8.x4.shared.b16 {%0,%1,%2,%3}, [%4];"
                 : "=r"(r[0]), "=r"(r[1]), "=r"(r[2]), "=r"(r[3]) : "r"(addr));
}
__device__ __forceinline__ void mma_bf16(float* c, const uint32_t* a,
                                         uint32_t b0, uint32_t b1) {
    asm volatile("mma.sync.aligned.m16n8k16.row.col.f32.bf16.bf16.f32 "
                 "{%0,%1,%2,%3}, {%4,%5,%6,%7}, {%8,%9}, {%0,%1,%2,%3};"
                 : "+f"(c[0]), "+f"(c[1]), "+f"(c[2]), "+f"(c[3])
                 : "r"(a[0]), "r"(a[1]), "r"(a[2]), "r"(a[3]), "r"(b0), "r"(b1));
}
// split a float into bf16 hi (round-half-up, 2 int ops) + fp32 residual
__device__ __forceinline__ uint32_t hi_bits(float x) {
    return (__float_as_uint(x) + 0x8000u) & 0xFFFF0000u;
}

// ---------------- smem layout (dynamic, 96 KB) ------------------------------------
#define OFF_WHI 0
#define OFF_WLO 32768
#define OFF_AHI 65536
#define OFF_ALO 81920
#define SMEM_TOTAL 98304

// ---------------- Phase 1: mma.sync bf16 3-pass GEMM + fused ssrc ------------------
__global__ __launch_bounds__(256, 2) void gemm_mma_kernel(const float* __restrict__ X,
                                                          const float* __restrict__ W,
                                                          const float* __restrict__ a_src,
                                                          int Ntot) {
    extern __shared__ char smem[];
    const uint32_t sb = smem_u32(smem);

    const int t    = threadIdx.x;
    const int lane = t & 31;
    const int wid  = t >> 5;
    const int row0 = blockIdx.x * 128;

    const int m0 = (wid & 3) * 32;
    const int n0 = (wid >> 2) * 32;

    const int srow = t >> 3, g = t & 7;
    const int r_lm  = (lane & 7) | (((lane >> 3) & 1) << 3);
    const int klane = ((lane >> 4) & 1) * 16;
    const int bn_lm = (lane & 7) + (((lane >> 4) & 1) << 3);
    const int bk_lm = ((lane >> 3) & 1) * 16;

    float sa8[8];
#pragma unroll
    for (int nt = 0; nt < 4; nt++) {
        int col = n0 + nt * 8 + ((lane & 3) << 1);
        sa8[2 * nt]     = __ldg(&a_src[col]);
        sa8[2 * nt + 1] = __ldg(&a_src[col + 1]);
    }

    // stage W: read fp32, split to bf16 hi/lo inline, swizzled per 128B row
#pragma unroll
    for (int i = 0; i < 8; i++) {
        int gidx = t + i * 256;                 // 16B bf16 block (= 8 k-elements)
        int n    = gidx >> 5;
        int rem  = (gidx & 31) * 16;
        int c    = rem >> 7;
        int kb   = rem & 127;
        const float* src = W + (size_t)n * DIN + (gidx & 31) * 8;
        float4 w0 = *(const float4*)(src);
        float4 w1 = *(const float4*)(src + 4);
        float f[8] = {w0.x, w0.y, w0.z, w0.w, w1.x, w1.y, w1.z, w1.w};
        uint32_t rh[4], rl[4];
#pragma unroll
        for (int q = 0; q < 4; q++) {
            uint32_t ha = hi_bits(f[2 * q]), hb = hi_bits(f[2 * q + 1]);
            rh[q] = __byte_perm(ha, hb, 0x7632);
            __nv_bfloat162 lo2 = __floats2bfloat162_rn(
                f[2 * q] - __uint_as_float(ha), f[2 * q + 1] - __uint_as_float(hb));
            rl[q] = *(uint32_t*)&lo2;
        }
        uint32_t so = (uint32_t)c * 8192 + SWZ128((uint32_t)n * 128 + kb);
        *(uint4*)(smem + OFF_WHI + so) = make_uint4(rh[0], rh[1], rh[2], rh[3]);
        *(uint4*)(smem + OFF_WLO + so) = make_uint4(rl[0], rl[1], rl[2], rl[3]);
    }

    float acc[2][4][4];
#pragma unroll
    for (int i = 0; i < 2; i++)
#pragma unroll
        for (int j = 0; j < 4; j++)
#pragma unroll
            for (int q = 0; q < 4; q++) acc[i][j][q] = 0.f;

    size_t grow[4];
#pragma unroll
    for (int p = 0; p < 4; p++) {
        int r = row0 + srow + 32 * p;
        grow[p] = (size_t)((r < Ntot) ? r : (Ntot - 1));
    }

    float4 va[4][2];
#pragma unroll
    for (int p = 0; p < 4; p++) {
        const float* src = X + grow[p] * DIN + g * 8;
        va[p][0] = *(const float4*)(src);
        va[p][1] = *(const float4*)(src + 4);
    }
#pragma unroll
    for (int p = 0; p < 4; p++) {
        uint32_t rh[4], rl[4];
        float f[8] = {va[p][0].x, va[p][0].y, va[p][0].z, va[p][0].w,
                      va[p][1].x, va[p][1].y, va[p][1].z, va[p][1].w};
#pragma unroll
        for (int q = 0; q < 4; q++) {
            uint32_t ha = hi_bits(f[2 * q]), hb = hi_bits(f[2 * q + 1]);
            rh[q] = __byte_perm(ha, hb, 0x7632);
            __nv_bfloat162 lo2 = __floats2bfloat162_rn(
                f[2 * q] - __uint_as_float(ha), f[2 * q + 1] - __uint_as_float(hb));
            rl[q] = *(uint32_t*)&lo2;
        }
        uint32_t bo = SWZ128((uint32_t)(srow + 32 * p) * 128 + g * 16);
        *(uint4*)(smem + OFF_AHI + bo) = make_uint4(rh[0], rh[1], rh[2], rh[3]);
        *(uint4*)(smem + OFF_ALO + bo) = make_uint4(rl[0], rl[1], rl[2], rl[3]);
    }
    __syncthreads();

    for (int c = 0; c < 4; c++) {
        if (c < 3) {
            const int kc = (c + 1) * 64;
#pragma unroll
            for (int p = 0; p < 4; p++) {
                const float* src = X + grow[p] * DIN + kc + g * 8;
                va[p][0] = *(const float4*)(src);
                va[p][1] = *(const float4*)(src + 4);
            }
        }
        const uint32_t ah_base = sb + OFF_AHI;
        const uint32_t al_base = sb + OFF_ALO;
        const uint32_t wh_base = sb + OFF_WHI + c * 8192;
        const uint32_t wl_base = sb + OFF_WLO + c * 8192;
#pragma unroll
        for (int ks = 0; ks < 4; ks++) {
            uint32_t ah[2][4], al[2][4], bh[8], bl[8];
#pragma unroll
            for (int mt = 0; mt < 2; mt++) {
                uint32_t bo = SWZ128((uint32_t)(m0 + mt * 16 + r_lm) * 128 +
                                     ks * 32 + klane);
                ldsm_x4(ah[mt], ah_base + bo);
                ldsm_x4(al[mt], al_base + bo);
            }
#pragma unroll
            for (int half = 0; half < 2; half++) {
                uint32_t bo = SWZ128((uint32_t)(n0 + half * 16 + bn_lm) * 128 +
                                     ks * 32 + bk_lm);
                ldsm_x4(bh + half * 4, wh_base + bo);
                ldsm_x4(bl + half * 4, wl_base + bo);
            }
#pragma unroll
            for (int nt = 0; nt < 4; nt++) {
                uint32_t bh0 = bh[2 * nt], bh1 = bh[2 * nt + 1];
                uint32_t bl0 = bl[2 * nt], bl1 = bl[2 * nt + 1];
#pragma unroll
                for (int mt = 0; mt < 2; mt++) {
                    mma_bf16(acc[mt][nt], ah[mt], bh0, bh1);
                    mma_bf16(acc[mt][nt], ah[mt], bl0, bl1);
                    mma_bf16(acc[mt][nt], al[mt], bh0, bh1);
                }
            }
        }
        if (c < 3) {
            __syncthreads();
#pragma unroll
            for (int p = 0; p < 4; p++) {
                uint32_t rh[4], rl[4];
                float f[8] = {va[p][0].x, va[p][0].y, va[p][0].z, va[p][0].w,
                              va[p][1].x, va[p][1].y, va[p][1].z, va[p][1].w};
#pragma unroll
                for (int q = 0; q < 4; q++) {
                    uint32_t ha = hi_bits(f[2 * q]), hb = hi_bits(f[2 * q + 1]);
                    rh[q] = __byte_perm(ha, hb, 0x7632);
                    __nv_bfloat162 lo2 = __floats2bfloat162_rn(
                        f[2 * q] - __uint_as_float(ha), f[2 * q + 1] - __uint_as_float(hb));
                    rl[q] = *(uint32_t*)&lo2;
                }
                uint32_t bo = SWZ128((uint32_t)(srow + 32 * p) * 128 + g * 16);
                *(uint4*)(smem + OFF_AHI + bo) = make_uint4(rh[0], rh[1], rh[2], rh[3]);
                *(uint4*)(smem + OFF_ALO + bo) = make_uint4(rl[0], rl[1], rl[2], rl[3]);
            }
            __syncthreads();
        }
    }

    // epilogue: fp16 stores + fused ssrc
#pragma unroll
    for (int mt = 0; mt < 2; mt++) {
        int r = row0 + m0 + mt * 16 + (lane >> 2);
#pragma unroll
        for (int nt = 0; nt < 4; nt++) {
            int col = n0 + nt * 8 + ((lane & 3) << 1);
            if (r < Ntot) {
                __half2 h = __floats2half2_rn(acc[mt][nt][0], acc[mt][nt][1]);
                *(__half2*)(g_eph + (size_t)r * DOUT + col) = h;
            }
            if (r + 8 < Ntot) {
                __half2 h = __floats2half2_rn(acc[mt][nt][2], acc[mt][nt][3]);
                *(__half2*)(g_eph + (size_t)(r + 8) * DOUT + col) = h;
            }
        }
    }
    __syncthreads();
    float* part = (float*)smem;
#pragma unroll
    for (int mt = 0; mt < 2; mt++) {
        float p0 = 0.f, p1 = 0.f;
#pragma unroll
        for (int nt = 0; nt < 4; nt++) {
            p0 = fmaf(acc[mt][nt][0], sa8[2 * nt], p0);
            p0 = fmaf(acc[mt][nt][1], sa8[2 * nt + 1], p0);
            p1 = fmaf(acc[mt][nt][2], sa8[2 * nt], p1);
            p1 = fmaf(acc[mt][nt][3], sa8[2 * nt + 1], p1);
        }
        p0 += __shfl_xor_sync(0xffffffffu, p0, 1);
        p0 += __shfl_xor_sync(0xffffffffu, p0, 2);
        p1 += __shfl_xor_sync(0xffffffffu, p1, 1);
        p1 += __shfl_xor_sync(0xffffffffu, p1, 2);
        if ((lane & 3) == 0) {
            int rl0 = m0 + mt * 16 + (lane >> 2);
            part[rl0 * 2 + (n0 >> 5)]       = p0;
            part[(rl0 + 8) * 2 + (n0 >> 5)] = p1;
        }
    }
    __syncthreads();
    if (t < 128) {
        int gr = row0 + t;
        if (gr < Ntot) {
            float s = part[t * 2] + part[t * 2 + 1];
            g_ssrc[gr] = (s >= 0.f) ? s : 0.2f * s;
        }
    }
}

// ---------------- mask dtype probe: bool(1B) vs int32 ----------------------------
__global__ void detect_kernel(const unsigned char* __restrict__ m) {
    int t = threadIdx.x;
    int f = 0;
    for (int i = t; i < 256; i += 32)
        if ((i & 3) && m[i]) f = 1;
    unsigned b = __ballot_sync(0xffffffffu, f);
    if (t == 0) g_mask_is_byte = (b != 0);
}

// ---------------- Phase 2: 2 rows/warp, 16 lanes/row, fp16 uint2 gathers ----------
__global__ __launch_bounds__(256) void agg_kernel(const int* __restrict__ neighs,
                                                  const void* __restrict__ mask_raw,
                                                  float* __restrict__ out,
                                                  int B, int L) {
    __shared__ float sw[8][2][64];
    __shared__ int   sidx[8][2][64];

    const int w    = threadIdx.x >> 5;
    const int lane = threadIdx.x & 31;
    const int half = lane >> 4;
    const int hl   = lane & 15;
    const int row  = (blockIdx.x * 8 + w) * 2 + half;
    const bool rv  = (row < B);
    const int rowc = rv ? row : 0;

    const bool maskb = (g_mask_is_byte != 0);
    const unsigned char* mk8  = (const unsigned char*)mask_raw + (size_t)rowc * L;
    const int*           mk32 = (const int*)mask_raw + (size_t)rowc * L;
    const int* nb = neighs + (size_t)rowc * L;

    int   ix[4];
    float s[4];
    bool  v[4];
#pragma unroll
    for (int j = 0; j < 4; j++) {
        int l = hl + 16 * j;
        v[j] = false; s[j] = -3e38f; ix[j] = 0;
        if (rv && l < L) {
            v[j] = maskb ? (mk8[l] != 0) : (mk32[l] != 0);
            if (v[j]) { ix[j] = nb[l]; s[j] = g_ssrc[ix[j]]; }
        }
    }

    float m = fmaxf(fmaxf(s[0], s[1]), fmaxf(s[2], s[3]));
#pragma unroll
    for (int o = 8; o; o >>= 1) m = fmaxf(m, __shfl_xor_sync(0xffffffffu, m, o));
    float e[4], ssum = 0.f;
#pragma unroll
    for (int j = 0; j < 4; j++) {
        e[j] = v[j] ? __expf(s[j] - m) : 0.f;
        ssum += e[j];
    }
#pragma unroll
    for (int o = 8; o; o >>= 1) ssum += __shfl_xor_sync(0xffffffffu, ssum, o);
    float inv = (ssum > 0.f) ? 1.0f / ssum : 0.f;

    unsigned bal[4];
#pragma unroll
    for (int j = 0; j < 4; j++) bal[j] = __ballot_sync(0xffffffffu, v[j]);
    const unsigned hmask = 0xFFFFu << (half * 16);
    const unsigned lt    = ((1u << lane) - 1u) & hmask;
    int cnt = 0;
#pragma unroll
    for (int j = 0; j < 4; j++) {
        if (v[j]) {
            int p = cnt + __popc(bal[j] & lt);
            sw[w][half][p]   = e[j] * inv;
            sidx[w][half][p] = ix[j];
        }
        cnt += __popc(bal[j] & hmask);
    }
    __syncwarp();

    int cmax = max(cnt, __shfl_xor_sync(0xffffffffu, cnt, 16));

    // gather: lane owns dims 4*hl..4*hl+3 of its row; LDG.64 (4 fp16) per neighbor
    float a0 = 0.f, a1 = 0.f, a2 = 0.f, a3 = 0.f;
    float b0 = 0.f, b1 = 0.f, b2 = 0.f, b3 = 0.f;
    const __half* ep = g_eph + 4 * hl;
    const float* swr = sw[w][half];
    const int*   sir = sidx[w][half];
    int l = 0;
    for (; l + 2 <= cmax; l += 2) {
        bool ok0 = (l < cnt), ok1 = (l + 1 < cnt);
        float w0 = ok0 ? swr[l]     : 0.f;
        float w1 = ok1 ? swr[l + 1] : 0.f;
        size_t j0 = ok0 ? (size_t)sir[l] * DOUT     : 0;
        size_t j1 = ok1 ? (size_t)sir[l + 1] * DOUT : 0;
        uint2 q0 = *(const uint2*)(ep + j0);
        uint2 q1 = *(const uint2*)(ep + j1);
        float2 f0a = __half22float2(*(__half2*)&q0.x);
        float2 f0b = __half22float2(*(__half2*)&q0.y);
        float2 f1a = __half22float2(*(__half2*)&q1.x);
        float2 f1b = __half22float2(*(__half2*)&q1.y);
        a0 = fmaf(w0, f0a.x, a0); a1 = fmaf(w0, f0a.y, a1);
        a2 = fmaf(w0, f0b.x, a2); a3 = fmaf(w0, f0b.y, a3);
        b0 = fmaf(w1, f1a.x, b0); b1 = fmaf(w1, f1a.y, b1);
        b2 = fmaf(w1, f1b.x, b2); b3 = fmaf(w1, f1b.y, b3);
    }
    if (l < cmax) {
        bool ok0 = (l < cnt);
        float w0 = ok0 ? swr[l] : 0.f;
        size_t j0 = ok0 ? (size_t)sir[l] * DOUT : 0;
        uint2 q0 = *(const uint2*)(ep + j0);
        float2 f0a = __half22float2(*(__half2*)&q0.x);
        float2 f0b = __half22float2(*(__half2*)&q0.y);
        a0 = fmaf(w0, f0a.x, a0); a1 = fmaf(w0, f0a.y, a1);
        a2 = fmaf(w0, f0b.x, a2); a3 = fmaf(w0, f0b.y, a3);
    }
    if (rv)
        *(float4*)(&out[(size_t)row * DOUT + 4 * hl]) =
            make_float4(a0 + b0, a1 + b1, a2 + b2, a3 + b3);
}

// -----------------------------------------------------------------------------------
extern "C" void kernel_launch(void* const* d_in, const int* in_sizes, int n_in,
                              void* d_out, int out_size) {
    const int*   neighs = (const int*)d_in[0];
    const void*  mask   = d_in[1];
    const float* embed  = (const float*)d_in[3];
    const float* W      = (const float*)d_in[4];
    const float* a_src  = (const float*)d_in[5];

    const int B = in_sizes[2];
    const int L = in_sizes[0] / B;
    const int N = in_sizes[3] / DIN;

    cudaFuncSetAttribute(gemm_mma_kernel,
                         cudaFuncAttributeMaxDynamicSharedMemorySize, SMEM_TOTAL);

    gemm_mma_kernel<<<(N + 127) / 128, 256, SMEM_TOTAL>>>(embed, W, a_src, N);
    detect_kernel<<<1, 32>>>((const unsigned char*)mask);
    agg_kernel<<<(B + 15) / 16, 256>>>(neighs, mask, (float*)d_out, B, L);
}